// round 3
// baseline (speedup 1.0000x reference)
#include <cuda_runtime.h>
#include <math.h>

#define NN 50000
#define NE 800000
#define D 128
#define LDA 128   // smem tile row stride (floats)
#define KC 16     // k-chunk staged per barrier phase

typedef unsigned long long u64;

// ---------------- scratch (device globals; no allocation allowed) ----------
__device__ float g_deg[NN];
__device__ float g_dinv[NN];
__device__ float g_xs[NN * D];        // dinv[i] * x[i]
__device__ float g_agg[NN * D];       // accumulated (A+I) * xs
__device__ float g_Bzrx[D * 256];     // [Wf_z | Wf_r]        (k-major, 256 cols)
__device__ float g_Bzrh[D * 256];     // [Wlz_bot | Wlr_bot]  (k-major, 256 cols)
__device__ float g_Wfh[D * D];        // Wf_hh
__device__ float g_bf[3 * D];         // fused biases z,r,hh

// ---------------- f32x2 helpers ---------------------------------------------
__device__ __forceinline__ u64 pk2(float x, float y) {
    u64 r; asm("mov.b64 %0,{%1,%2};" : "=l"(r) : "f"(x), "f"(y)); return r;
}
__device__ __forceinline__ void f2(u64& d, u64 a, u64 b) {
    asm("fma.rn.f32x2 %0, %1, %2, %0;" : "+l"(d) : "l"(a), "l"(b));
}
__device__ __forceinline__ float hadd(u64 v) {
    float x, y; asm("mov.b64 {%0,%1},%2;" : "=f"(x), "=f"(y) : "l"(v)); return x + y;
}
__device__ __forceinline__ float sigm(float x) { return 1.0f / (1.0f + expf(-x)); }

// ---------------- degree -----------------------------------------------------
__global__ void k_init_deg() {
    int i = blockIdx.x * blockDim.x + threadIdx.x;
    if (i < NN) g_deg[i] = 1.0f;  // self-loop
}

__global__ void k_count(const int* __restrict__ dst) {
    int e = blockIdx.x * blockDim.x + threadIdx.x;
    if (e < NE) atomicAdd(&g_deg[dst[e]], 1.0f);
}

// xs = dinv * x ; agg initialized with self-loop term (= xs)
__global__ void k_prescale(const float* __restrict__ x) {
    int idx = blockIdx.x * blockDim.x + threadIdx.x;
    if (idx >= NN * 32) return;
    int i = idx >> 5, c = idx & 31;
    float dv = rsqrtf(g_deg[i]);
    float4 v = ((const float4*)x)[idx];
    v.x *= dv; v.y *= dv; v.z *= dv; v.w *= dv;
    ((float4*)g_xs)[idx] = v;
    ((float4*)g_agg)[idx] = v;
    if (c == 0) g_dinv[i] = dv;
}

// warp per edge: gather xs[src] (L2-resident), vector-red into agg[dst]
__global__ void k_edges(const int* __restrict__ src, const int* __restrict__ dst) {
    int idx = blockIdx.x * blockDim.x + threadIdx.x;
    if (idx >= NE * 32) return;
    int e = idx >> 5, lane = idx & 31;
    int s = __ldg(&src[e]);
    int d2 = __ldg(&dst[e]);
    float4 v = ((const float4*)g_xs)[s * 32 + lane];
    float4* p = ((float4*)g_agg) + d2 * 32 + lane;
    asm volatile("red.global.add.v4.f32 [%0], {%1,%2,%3,%4};"
                 :: "l"(p), "f"(v.x), "f"(v.y), "f"(v.z), "f"(v.w) : "memory");
}

// ---------------- fused weight precompute -----------------------------------
// Wf_g = Wc_g @ Wl_g[0:128,:]; z/r packed side-by-side into 256-col layout.
__global__ void k_fuse(const float* __restrict__ Wc_z, const float* __restrict__ Wl_z,
                       const float* __restrict__ bc_z, const float* __restrict__ bl_z,
                       const float* __restrict__ Wc_r, const float* __restrict__ Wl_r,
                       const float* __restrict__ bc_r, const float* __restrict__ bl_r,
                       const float* __restrict__ Wc_h, const float* __restrict__ Wl_h,
                       const float* __restrict__ bc_h, const float* __restrict__ bl_h) {
    int g = blockIdx.y;
    const float* Wc = (g == 0) ? Wc_z : (g == 1) ? Wc_r : Wc_h;
    const float* Wl = (g == 0) ? Wl_z : (g == 1) ? Wl_r : Wl_h;
    const float* bc = (g == 0) ? bc_z : (g == 1) ? bc_r : bc_h;
    const float* bl = (g == 0) ? bl_z : (g == 1) ? bl_r : bl_h;
    int i = blockIdx.x;
    int j = threadIdx.x;
    float s = 0.0f;
    #pragma unroll 8
    for (int k = 0; k < D; ++k) s += Wc[i * D + k] * Wl[k * D + j];
    if (g < 2) g_Bzrx[i * 256 + g * D + j] = s;
    else       g_Wfh[i * D + j] = s;
    if (i == 0) {
        float b = bl[j];
        #pragma unroll 8
        for (int k = 0; k < D; ++k) b += bc[k] * Wl[k * D + j];
        g_bf[g * D + j] = b;
    }
}

// concat bottom halves of Wl_z / Wl_r into 256-col layout
__global__ void k_catB(const float* __restrict__ Wl_z, const float* __restrict__ Wl_r) {
    int k = blockIdx.x;
    int j = threadIdx.x;  // 0..255
    const float* W = (j < D) ? Wl_z : Wl_r;
    g_Bzrh[k * 256 + j] = W[(D + k) * D + (j & (D - 1))];
}

// ---------------- main fused GRU tile kernel --------------------------------
// 256 threads, 128-node tile. Thread grid 16(tm: 8 rows each) x 16(tn).
// FFMA2 GEMM: acc pairs accumulate even-k in .lo, odd-k in .hi.
template <int W>
__device__ __forceinline__ void gemm2(const float* __restrict__ As,
                                      const float* __restrict__ Bg,
                                      u64* acc, u64* Bs2,
                                      int tid, int tm, int tn) {
    const int NC = W / 16;  // cols per thread
    #pragma unroll 1
    for (int kc = 0; kc < D; kc += KC) {
        // stage B chunk as k-pairs: Bs2[kp][j] = (B[kc+2kp][j], B[kc+2kp+1][j])
        #pragma unroll
        for (int e = tid; e < 8 * W; e += 256) {
            int kp = e / W, j = e % W;
            Bs2[kp * W + j] = pk2(Bg[(kc + 2 * kp) * W + j],
                                  Bg[(kc + 2 * kp + 1) * W + j]);
        }
        __syncthreads();
        #pragma unroll
        for (int kp = 0; kp < KC / 2; ++kp) {
            u64 bv[NC];
            #pragma unroll
            for (int p = 0; p < NC; ++p) bv[p] = Bs2[kp * W + p * 16 + tn];
            #pragma unroll
            for (int i = 0; i < 8; ++i) {
                u64 av = *(const u64*)(As + (tm * 8 + i) * LDA + kc + kp * 2);
                #pragma unroll
                for (int p = 0; p < NC; ++p) f2(acc[i * NC + p], av, bv[p]);
            }
        }
        __syncthreads();
    }
}

__global__ void __launch_bounds__(256, 1)
k_main(const float* __restrict__ h,
       const float* __restrict__ Wl_h,
       const float* __restrict__ W_lin, const float* __restrict__ b_lin,
       float* __restrict__ out) {
    extern __shared__ float sm[];
    float* xa = sm;                  // 128x128 x_agg tile (scaled)
    float* hs = sm + D * LDA;        // 128x128 h tile -> relu(h0)
    float* hr = sm + 2 * D * LDA;    // 128x128 h*R -> h0 staging
    u64*  Bs2 = (u64*)(sm + 3 * D * LDA);   // 8 x 256 u64 (16KB)
    float* sb = sm + 3 * D * LDA + 4096;    // 512 bias floats

    int tid = threadIdx.x;
    int tm = tid >> 4, tn = tid & 15;
    int nb = blockIdx.x * D;

    // load tiles + biases
    for (int idx = tid; idx < D * 32; idx += 256) {
        int r = idx >> 5, c = idx & 31;
        int node = nb + r;
        float4 va = {0, 0, 0, 0}, vh = {0, 0, 0, 0};
        if (node < NN) {
            float dv = g_dinv[node];
            va = ((const float4*)g_agg)[node * 32 + c];
            va.x *= dv; va.y *= dv; va.z *= dv; va.w *= dv;
            vh = ((const float4*)h)[node * 32 + c];
        }
        *((float4*)(xa + r * LDA) + c) = va;
        *((float4*)(hs + r * LDA) + c) = vh;
    }
    // biases: sb[0..383] = g_bf (z,r,hh), sb[384..511] = b_lin
    for (int q = tid; q < 512; q += 256)
        sb[q] = (q < 3 * D) ? g_bf[q] : b_lin[q - 3 * D];
    __syncthreads();

    // ---- stage 1+2 merged: [Zpre | Rpre] = xa@[Wf_z|Wf_r] + hs@[Wlz_b|Wlr_b]
    {
        u64 acc[8 * 16];
        #pragma unroll
        for (int q = 0; q < 128; ++q) acc[q] = 0ULL;
        gemm2<256>(xa, g_Bzrx, acc, Bs2, tid, tm, tn);
        gemm2<256>(hs, g_Bzrh, acc, Bs2, tid, tm, tn);

        float Zr[8][8];
        #pragma unroll
        for (int i = 0; i < 8; ++i) {
            int m = tm * 8 + i;
            #pragma unroll
            for (int p = 0; p < 8; ++p) {
                int c = p * 16 + tn;
                float z = sigm(hadd(acc[i * 16 + p]) + sb[c]);
                float r = sigm(hadd(acc[i * 16 + p + 8]) + sb[D + c]);
                Zr[i][p] = z;
                hr[m * LDA + c] = hs[m * LDA + c] * r;
            }
        }
        __syncthreads();

        // ---- stage 3: Ht = tanh(xa@Wf_h + hr@Wlh_bot + bf_h); h0 blend
        u64* a2 = acc;  // reuse first 64
        #pragma unroll
        for (int q = 0; q < 64; ++q) a2[q] = 0ULL;
        gemm2<128>(xa, g_Wfh, a2, Bs2, tid, tm, tn);
        gemm2<128>(hr, Wl_h + D * D, a2, Bs2, tid, tm, tn);

        #pragma unroll
        for (int i = 0; i < 8; ++i) {
            int m = tm * 8 + i;
            #pragma unroll
            for (int p = 0; p < 8; ++p) {
                int c = p * 16 + tn;
                float Ht = tanhf(hadd(a2[i * 8 + p]) + sb[2 * D + c]);
                float z = Zr[i][p];
                float hv = hs[m * LDA + c];
                float h0 = z * hv + (1.0f - z) * Ht;
                hr[m * LDA + c] = h0;              // stage h0 for bulk store
                hs[m * LDA + c] = fmaxf(h0, 0.0f); // relu(h0)
            }
        }
        __syncthreads();
    }

    // bulk store h0 (coalesced float4)
    {
        float* out_h = out + (long long)NN * D;
        for (int idx = tid; idx < D * 32; idx += 256) {
            int r = idx >> 5, c = idx & 31;
            int node = nb + r;
            if (node < NN)
                ((float4*)out_h)[node * 32 + c] = *((float4*)(hr + r * LDA) + c);
        }
    }

    // ---- stage 4: z_out = relu(h0) @ W_lin + b_lin
    {
        u64 acc[8 * 8];
        #pragma unroll
        for (int q = 0; q < 64; ++q) acc[q] = 0ULL;
        gemm2<128>(hs, W_lin, acc, Bs2, tid, tm, tn);
        #pragma unroll
        for (int i = 0; i < 8; ++i) {
            int m = tm * 8 + i;
            #pragma unroll
            for (int p = 0; p < 8; ++p) {
                int c = p * 16 + tn;
                xa[m * LDA + c] = hadd(acc[i * 8 + p]) + sb[3 * D + c];
            }
        }
        __syncthreads();
        for (int idx = tid; idx < D * 32; idx += 256) {
            int r = idx >> 5, c = idx & 31;
            int node = nb + r;
            if (node < NN)
                ((float4*)out)[node * 32 + c] = *((float4*)(xa + r * LDA) + c);
        }
    }
}

// ---------------- launch -----------------------------------------------------
extern "C" void kernel_launch(void* const* d_in, const int* in_sizes, int n_in,
                              void* d_out, int out_size) {
    const float* node_feat = (const float*)d_in[0];
    const int*   src       = (const int*)d_in[1];
    const int*   dst       = (const int*)d_in[2];
    const float* h         = (const float*)d_in[3];
    const float* Wc_z = (const float*)d_in[4];
    const float* bc_z = (const float*)d_in[5];
    const float* Wl_z = (const float*)d_in[6];
    const float* bl_z = (const float*)d_in[7];
    const float* Wc_r = (const float*)d_in[8];
    const float* bc_r = (const float*)d_in[9];
    const float* Wl_r = (const float*)d_in[10];
    const float* bl_r = (const float*)d_in[11];
    const float* Wc_h = (const float*)d_in[12];
    const float* bc_h = (const float*)d_in[13];
    const float* Wl_h = (const float*)d_in[14];
    const float* bl_h = (const float*)d_in[15];
    const float* W_lin = (const float*)d_in[16];
    const float* b_lin = (const float*)d_in[17];
    float* out = (float*)d_out;

    const int smem = (3 * D * LDA + 4096 + 512) * sizeof(float);
    cudaFuncSetAttribute(k_main, cudaFuncAttributeMaxDynamicSharedMemorySize, smem);

    k_init_deg<<<(NN + 255) / 256, 256>>>();
    k_count<<<(NE + 255) / 256, 256>>>(dst);
    k_prescale<<<(NN * 32 + 255) / 256, 256>>>(node_feat);
    k_edges<<<(NE * 32) / 256, 256>>>(src, dst);
    k_fuse<<<dim3(D, 3), D>>>(Wc_z, Wl_z, bc_z, bl_z,
                              Wc_r, Wl_r, bc_r, bl_r,
                              Wc_h, Wl_h, bc_h, bl_h);
    k_catB<<<D, 256>>>(Wl_z, Wl_r);
    k_main<<<(NN + D - 1) / D, 256, smem>>>(h, Wl_h, W_lin, b_lin, out);
}

// round 4
// speedup vs baseline: 2.6158x; 2.6158x over previous
#include <cuda_runtime.h>
#include <math.h>

#define NN 50000
#define NE 800000
#define D 128
#define KC 16     // k-chunk staged per barrier phase

typedef unsigned long long u64;

// ---------------- scratch (device globals; no allocation allowed) ----------
__device__ float g_deg[NN];
__device__ float g_dinv[NN];
__device__ float g_xs[NN * D];     // dinv[i] * x[i]
__device__ float g_agg[NN * D];    // accumulated (A+I) * xs
__device__ float g_Wf[3 * D * D];  // fused Wc_g @ Wl_g_top  (z, r, hh)
__device__ float g_bf[3 * D];      // fused bc_g @ Wl_g_top + bl_g

// ---------------- f32x2 helpers ---------------------------------------------
__device__ __forceinline__ u64 pk2(float x, float y) {
    u64 r; asm("mov.b64 %0,{%1,%2};" : "=l"(r) : "f"(x), "f"(y)); return r;
}
__device__ __forceinline__ void f2(u64& d, u64 a, u64 b) {
    asm("fma.rn.f32x2 %0, %1, %2, %0;" : "+l"(d) : "l"(a), "l"(b));
}
__device__ __forceinline__ float hadd(u64 v) {
    float x, y; asm("mov.b64 {%0,%1},%2;" : "=f"(x), "=f"(y) : "l"(v)); return x + y;
}
__device__ __forceinline__ float sigm(float x) { return 1.0f / (1.0f + expf(-x)); }

// ---------------- degree -----------------------------------------------------
__global__ void k_init_deg() {
    int i = blockIdx.x * blockDim.x + threadIdx.x;
    if (i < NN) g_deg[i] = 1.0f;  // self-loop
}

__global__ void k_count(const int* __restrict__ dst) {
    int e = blockIdx.x * blockDim.x + threadIdx.x;
    if (e < NE) atomicAdd(&g_deg[dst[e]], 1.0f);
}

// xs = dinv * x ; agg initialized with self-loop term (= xs)
__global__ void k_prescale(const float* __restrict__ x) {
    int idx = blockIdx.x * blockDim.x + threadIdx.x;
    if (idx >= NN * 32) return;
    int i = idx >> 5, c = idx & 31;
    float dv = rsqrtf(g_deg[i]);
    float4 v = ((const float4*)x)[idx];
    v.x *= dv; v.y *= dv; v.z *= dv; v.w *= dv;
    ((float4*)g_xs)[idx] = v;
    ((float4*)g_agg)[idx] = v;
    if (c == 0) g_dinv[i] = dv;
}

// warp per edge: gather xs[src] (L2-resident), vector-red into agg[dst]
__global__ void k_edges(const int* __restrict__ src, const int* __restrict__ dst) {
    int idx = blockIdx.x * blockDim.x + threadIdx.x;
    if (idx >= NE * 32) return;
    int e = idx >> 5, lane = idx & 31;
    int s = __ldg(&src[e]);
    int d2 = __ldg(&dst[e]);
    float4 v = ((const float4*)g_xs)[s * 32 + lane];
    float4* p = ((float4*)g_agg) + d2 * 32 + lane;
    asm volatile("red.global.add.v4.f32 [%0], {%1,%2,%3,%4};"
                 :: "l"(p), "f"(v.x), "f"(v.y), "f"(v.z), "f"(v.w) : "memory");
}

// ---------------- fused weight precompute: Wf_g = Wc_g @ Wl_g[0:128,:] ------
__global__ void k_fuse(const float* __restrict__ Wc_z, const float* __restrict__ Wl_z,
                       const float* __restrict__ bc_z, const float* __restrict__ bl_z,
                       const float* __restrict__ Wc_r, const float* __restrict__ Wl_r,
                       const float* __restrict__ bc_r, const float* __restrict__ bl_r,
                       const float* __restrict__ Wc_h, const float* __restrict__ Wl_h,
                       const float* __restrict__ bc_h, const float* __restrict__ bl_h) {
    int g = blockIdx.y;
    const float* Wc = (g == 0) ? Wc_z : (g == 1) ? Wc_r : Wc_h;
    const float* Wl = (g == 0) ? Wl_z : (g == 1) ? Wl_r : Wl_h;
    const float* bc = (g == 0) ? bc_z : (g == 1) ? bc_r : bc_h;
    const float* bl = (g == 0) ? bl_z : (g == 1) ? bl_r : bl_h;
    int i = blockIdx.x;
    int j = threadIdx.x;
    float s = 0.0f;
    #pragma unroll 8
    for (int k = 0; k < D; ++k) s += Wc[i * D + k] * Wl[k * D + j];
    g_Wf[g * D * D + i * D + j] = s;
    if (i == 0) {
        float b = bl[j];
        #pragma unroll 8
        for (int k = 0; k < D; ++k) b += bc[k] * Wl[k * D + j];
        g_bf[g * D + j] = b;
    }
}

// ---------------- main fused GRU tile kernel --------------------------------
// 512 threads, 128-node tile. tm = tid>>4 (32 groups x 4 rows), tn = tid&15.
// FFMA2 GEMM: each acc u64 holds (even-k partial, odd-k partial).
__device__ __forceinline__ void gemm2(const float* __restrict__ As,
                                      const float* __restrict__ Bg,
                                      u64* acc, u64* Bs2,
                                      int tid, int tm, int tn) {
    #pragma unroll 1
    for (int kc = 0; kc < D; kc += KC) {
        // stage B k-pairs: Bs2[kp*128 + j] = (B[kc+2kp][j], B[kc+2kp+1][j])
        #pragma unroll
        for (int e = tid; e < (KC / 2) * D; e += 512) {
            int kp = e >> 7, j = e & 127;
            Bs2[e] = pk2(Bg[(kc + 2 * kp) * D + j],
                         Bg[(kc + 2 * kp + 1) * D + j]);
        }
        __syncthreads();
        #pragma unroll
        for (int kp = 0; kp < KC / 2; ++kp) {
            u64 bv[8];
            #pragma unroll
            for (int p = 0; p < 8; ++p) bv[p] = Bs2[kp * D + p * 16 + tn];
            #pragma unroll
            for (int i = 0; i < 4; ++i) {
                u64 av = *(const u64*)(As + (tm * 4 + i) * D + kc + kp * 2);
                #pragma unroll
                for (int p = 0; p < 8; ++p) f2(acc[i * 8 + p], av, bv[p]);
            }
        }
        __syncthreads();
    }
}

__global__ void __launch_bounds__(512, 1)
k_main(const float* __restrict__ h,
       const float* __restrict__ Wl_z, const float* __restrict__ Wl_r,
       const float* __restrict__ Wl_h,
       const float* __restrict__ W_lin, const float* __restrict__ b_lin,
       float* __restrict__ out) {
    extern __shared__ float sm[];
    float* xa = sm;                  // 128x128 x_agg tile (scaled)
    float* hs = sm + D * D;          // 128x128 h tile -> relu(h0)
    float* hr = sm + 2 * D * D;      // 128x128 h*R -> h0 staging
    u64*  Bs2 = (u64*)(sm + 3 * D * D);    // 8 x 128 u64 (8KB)
    float* sb = sm + 3 * D * D + 2048;     // 512 bias floats

    int tid = threadIdx.x;
    int tm = tid >> 4, tn = tid & 15;
    int nb = blockIdx.x * D;

    // load tiles + biases
    for (int idx = tid; idx < D * 32; idx += 512) {
        int r = idx >> 5, c = idx & 31;
        int node = nb + r;
        float4 va = {0, 0, 0, 0}, vh = {0, 0, 0, 0};
        if (node < NN) {
            float dv = g_dinv[node];
            va = ((const float4*)g_agg)[node * 32 + c];
            va.x *= dv; va.y *= dv; va.z *= dv; va.w *= dv;
            vh = ((const float4*)h)[node * 32 + c];
        }
        *((float4*)(xa + r * D) + c) = va;
        *((float4*)(hs + r * D) + c) = vh;
    }
    // biases: sb[0..383] = g_bf (z,r,hh), sb[384..511] = b_lin
    for (int q = tid; q < 512; q += 512)
        sb[q] = (q < 3 * D) ? g_bf[q] : b_lin[q - 3 * D];
    __syncthreads();

    u64 acc[32];
    float Zr[4][8];

    // ---- stage Z: Z = sigmoid(xa@Wf_z + hs@Wlz_bot + bf_z)
    #pragma unroll
    for (int q = 0; q < 32; ++q) acc[q] = 0ULL;
    gemm2(xa, g_Wf, acc, Bs2, tid, tm, tn);
    gemm2(hs, Wl_z + D * D, acc, Bs2, tid, tm, tn);
    #pragma unroll
    for (int i = 0; i < 4; ++i)
        #pragma unroll
        for (int p = 0; p < 8; ++p)
            Zr[i][p] = sigm(hadd(acc[i * 8 + p]) + sb[p * 16 + tn]);

    // ---- stage R: R = sigmoid(xa@Wf_r + hs@Wlr_bot + bf_r); hr = h*R
    #pragma unroll
    for (int q = 0; q < 32; ++q) acc[q] = 0ULL;
    gemm2(xa, g_Wf + D * D, acc, Bs2, tid, tm, tn);
    gemm2(hs, Wl_r + D * D, acc, Bs2, tid, tm, tn);
    #pragma unroll
    for (int i = 0; i < 4; ++i) {
        int m = tm * 4 + i;
        #pragma unroll
        for (int p = 0; p < 8; ++p) {
            int c = p * 16 + tn;
            float r = sigm(hadd(acc[i * 8 + p]) + sb[D + c]);
            hr[m * D + c] = hs[m * D + c] * r;
        }
    }
    __syncthreads();

    // ---- stage H: Ht = tanh(xa@Wf_h + hr@Wlh_bot + bf_h); h0 blend
    #pragma unroll
    for (int q = 0; q < 32; ++q) acc[q] = 0ULL;
    gemm2(xa, g_Wf + 2 * D * D, acc, Bs2, tid, tm, tn);
    gemm2(hr, Wl_h + D * D, acc, Bs2, tid, tm, tn);
    #pragma unroll
    for (int i = 0; i < 4; ++i) {
        int m = tm * 4 + i;
        #pragma unroll
        for (int p = 0; p < 8; ++p) {
            int c = p * 16 + tn;
            float Ht = tanhf(hadd(acc[i * 8 + p]) + sb[2 * D + c]);
            float z = Zr[i][p];
            float hv = hs[m * D + c];
            float h0 = z * hv + (1.0f - z) * Ht;
            hr[m * D + c] = h0;              // stage h0 for bulk store
            hs[m * D + c] = fmaxf(h0, 0.0f); // relu(h0)
        }
    }
    __syncthreads();

    // bulk store h0 (coalesced float4)
    {
        float* out_h = out + (long long)NN * D;
        for (int idx = tid; idx < D * 32; idx += 512) {
            int r = idx >> 5, c = idx & 31;
            int node = nb + r;
            if (node < NN)
                ((float4*)out_h)[node * 32 + c] = *((float4*)(hr + r * D) + c);
        }
    }

    // ---- stage L: z_out = relu(h0) @ W_lin + b_lin
    #pragma unroll
    for (int q = 0; q < 32; ++q) acc[q] = 0ULL;
    gemm2(hs, W_lin, acc, Bs2, tid, tm, tn);
    #pragma unroll
    for (int i = 0; i < 4; ++i) {
        int m = tm * 4 + i;
        #pragma unroll
        for (int p = 0; p < 8; ++p) {
            int c = p * 16 + tn;
            xa[m * D + c] = hadd(acc[i * 8 + p]) + sb[3 * D + c];
        }
    }
    __syncthreads();
    for (int idx = tid; idx < D * 32; idx += 512) {
        int r = idx >> 5, c = idx & 31;
        int node = nb + r;
        if (node < NN)
            ((float4*)out)[node * 32 + c] = *((float4*)(xa + r * D) + c);
    }
}

// ---------------- launch -----------------------------------------------------
extern "C" void kernel_launch(void* const* d_in, const int* in_sizes, int n_in,
                              void* d_out, int out_size) {
    const float* node_feat = (const float*)d_in[0];
    const int*   src       = (const int*)d_in[1];
    const int*   dst       = (const int*)d_in[2];
    const float* h         = (const float*)d_in[3];
    const float* Wc_z = (const float*)d_in[4];
    const float* bc_z = (const float*)d_in[5];
    const float* Wl_z = (const float*)d_in[6];
    const float* bl_z = (const float*)d_in[7];
    const float* Wc_r = (const float*)d_in[8];
    const float* bc_r = (const float*)d_in[9];
    const float* Wl_r = (const float*)d_in[10];
    const float* bl_r = (const float*)d_in[11];
    const float* Wc_h = (const float*)d_in[12];
    const float* bc_h = (const float*)d_in[13];
    const float* Wl_h = (const float*)d_in[14];
    const float* bl_h = (const float*)d_in[15];
    const float* W_lin = (const float*)d_in[16];
    const float* b_lin = (const float*)d_in[17];
    float* out = (float*)d_out;

    const int smem = (3 * D * D + 2048 + 512) * sizeof(float);
    cudaFuncSetAttribute(k_main, cudaFuncAttributeMaxDynamicSharedMemorySize, smem);

    k_init_deg<<<(NN + 255) / 256, 256>>>();
    k_count<<<(NE + 255) / 256, 256>>>(dst);
    k_prescale<<<(NN * 32 + 255) / 256, 256>>>(node_feat);
    k_edges<<<(NE * 32) / 256, 256>>>(src, dst);
    k_fuse<<<dim3(D, 3), D>>>(Wc_z, Wl_z, bc_z, bl_z,
                              Wc_r, Wl_r, bc_r, bl_r,
                              Wc_h, Wl_h, bc_h, bl_h);
    k_main<<<(NN + D - 1) / D, 512, smem>>>(h, Wl_z, Wl_r, Wl_h, W_lin, b_lin, out);
}

// round 6
// speedup vs baseline: 4.1353x; 1.5809x over previous
#include <cuda_runtime.h>
#include <cuda_bf16.h>
#include <mma.h>
#include <math.h>

#define NN 50000
#define NE 800000
#define D 128
#define PA 136            // padded panel row (bf16 elems), 272B rows
#define PAB (PA * 2)      // panel row bytes

// smem byte offsets
#define XA_HI 0
#define XA_LO 34816
#define H_HI  69632
#define H_LO  104448
#define BS_HI 139264
#define BS_LO 174080
#define SCR   139264      // f32 scratch (128x132), overlays B region after sync
#define SB    208896      // 512 f32 biases
#define SM_TOTAL (208896 + 2048)

typedef unsigned int u32;
using namespace nvcuda;
typedef wmma::fragment<wmma::matrix_a, 16, 16, 16, __nv_bfloat16, wmma::row_major> FragA;
typedef wmma::fragment<wmma::matrix_b, 16, 16, 16, __nv_bfloat16, wmma::row_major> FragB;
typedef wmma::fragment<wmma::accumulator, 16, 16, 16, float> FragC;

// ---------------- scratch (device globals; no allocation allowed) ----------
__device__ float g_deg[NN];
__device__ float g_dinv[NN];
__device__ float g_xs[NN * D];
__device__ float g_agg[NN * D];
__device__ float g_Wf[3 * D * D];   // fused Wc_g @ Wl_g_top (f32), [k][n]
__device__ float g_bf[3 * D];       // fused biases
// 7 B mats (Wfz, Wlzb, Wfr, Wlrb, Wfh, Wlhb, Wlin), [k][n] bf16, hi then lo
__device__ __nv_bfloat16 g_B[7 * 32768];

__device__ __forceinline__ float sigm(float x) { return 1.0f / (1.0f + expf(-x)); }
__device__ __forceinline__ void split2(float x0, float x1, u32& hi, u32& lo) {
    __nv_bfloat16 h0 = __float2bfloat16(x0), h1 = __float2bfloat16(x1);
    __nv_bfloat16 l0 = __float2bfloat16(x0 - __bfloat162float(h0));
    __nv_bfloat16 l1 = __float2bfloat16(x1 - __bfloat162float(h1));
    hi = (u32)__bfloat16_as_ushort(h0) | ((u32)__bfloat16_as_ushort(h1) << 16);
    lo = (u32)__bfloat16_as_ushort(l0) | ((u32)__bfloat16_as_ushort(l1) << 16);
}

// ---------------- graph prep kernels ----------------------------------------
__global__ void k_init_deg() {
    int i = blockIdx.x * blockDim.x + threadIdx.x;
    if (i < NN) g_deg[i] = 1.0f;
}
__global__ void k_count(const int* __restrict__ dst) {
    int e = blockIdx.x * blockDim.x + threadIdx.x;
    if (e < NE) atomicAdd(&g_deg[dst[e]], 1.0f);
}
__global__ void k_prescale(const float* __restrict__ x) {
    int idx = blockIdx.x * blockDim.x + threadIdx.x;
    if (idx >= NN * 32) return;
    int i = idx >> 5, c = idx & 31;
    float dv = rsqrtf(g_deg[i]);
    float4 v = ((const float4*)x)[idx];
    v.x *= dv; v.y *= dv; v.z *= dv; v.w *= dv;
    ((float4*)g_xs)[idx] = v;
    ((float4*)g_agg)[idx] = v;
    if (c == 0) g_dinv[i] = dv;
}
__global__ void k_edges(const int* __restrict__ src, const int* __restrict__ dst) {
    int idx = blockIdx.x * blockDim.x + threadIdx.x;
    if (idx >= NE * 32) return;
    int e = idx >> 5, lane = idx & 31;
    int s = __ldg(&src[e]);
    int d2 = __ldg(&dst[e]);
    float4 v = ((const float4*)g_xs)[s * 32 + lane];
    float4* p = ((float4*)g_agg) + d2 * 32 + lane;
    asm volatile("red.global.add.v4.f32 [%0], {%1,%2,%3,%4};"
                 :: "l"(p), "f"(v.x), "f"(v.y), "f"(v.z), "f"(v.w) : "memory");
}

// ---------------- weight fusion + bf16 split ---------------------------------
__global__ void k_fuse(const float* __restrict__ Wc_z, const float* __restrict__ Wl_z,
                       const float* __restrict__ bc_z, const float* __restrict__ bl_z,
                       const float* __restrict__ Wc_r, const float* __restrict__ Wl_r,
                       const float* __restrict__ bc_r, const float* __restrict__ bl_r,
                       const float* __restrict__ Wc_h, const float* __restrict__ Wl_h,
                       const float* __restrict__ bc_h, const float* __restrict__ bl_h) {
    int g = blockIdx.y;
    const float* Wc = (g == 0) ? Wc_z : (g == 1) ? Wc_r : Wc_h;
    const float* Wl = (g == 0) ? Wl_z : (g == 1) ? Wl_r : Wl_h;
    const float* bc = (g == 0) ? bc_z : (g == 1) ? bc_r : bc_h;
    const float* bl = (g == 0) ? bl_z : (g == 1) ? bl_r : bl_h;
    int i = blockIdx.x;
    int j = threadIdx.x;
    float s = 0.0f;
    #pragma unroll 8
    for (int k = 0; k < D; ++k) s += Wc[i * D + k] * Wl[k * D + j];
    g_Wf[g * D * D + i * D + j] = s;
    if (i == 0) {
        float b = bl[j];
        #pragma unroll 8
        for (int k = 0; k < D; ++k) b += bc[k] * Wl[k * D + j];
        g_bf[g * D + j] = b;
    }
}

__global__ void k_prep(const float* __restrict__ Wl_z, const float* __restrict__ Wl_r,
                       const float* __restrict__ Wl_h, const float* __restrict__ W_lin) {
    int idx = blockIdx.x * blockDim.x + threadIdx.x;
    if (idx >= 7 * D * D) return;
    int m = idx / (D * D);
    int r = idx % (D * D);
    int k = r / D, n = r % D;
    float w;
    switch (m) {
        case 0: w = g_Wf[k * D + n]; break;
        case 1: w = Wl_z[(D + k) * D + n]; break;
        case 2: w = g_Wf[D * D + k * D + n]; break;
        case 3: w = Wl_r[(D + k) * D + n]; break;
        case 4: w = g_Wf[2 * D * D + k * D + n]; break;
        case 5: w = Wl_h[(D + k) * D + n]; break;
        default: w = W_lin[k * D + n]; break;
    }
    __nv_bfloat16 hi = __float2bfloat16(w);
    __nv_bfloat16 lo = __float2bfloat16(w - __bfloat162float(hi));
    g_B[m * 32768 + k * D + n] = hi;
    g_B[m * 32768 + 16384 + k * D + n] = lo;
}

// ---------------- main fused GRU kernel (HMMA wmma bf16 split) --------------
__device__ __forceinline__ void copyB(char* smem, int mat, int tid) {
    const char* src = (const char*)g_B + mat * 65536;
    #pragma unroll
    for (int e = tid; e < 2048; e += 512) {  // 128 rows x 16 chunks of 16B
        int r = e >> 4, c = e & 15;
        *(float4*)(smem + BS_HI + r * PAB + c * 16) =
            *(const float4*)(src + r * 256 + c * 16);
        *(float4*)(smem + BS_LO + r * PAB + c * 16) =
            *(const float4*)(src + 32768 + r * 256 + c * 16);
    }
}

__device__ __forceinline__ void gemm_mat(const char* smem, int a_hi, int a_lo,
                                         FragC acc[2][2], int wm, int wn) {
    const __nv_bfloat16* pah = (const __nv_bfloat16*)(smem + a_hi);
    const __nv_bfloat16* pal = (const __nv_bfloat16*)(smem + a_lo);
    const __nv_bfloat16* pbh = (const __nv_bfloat16*)(smem + BS_HI);
    const __nv_bfloat16* pbl = (const __nv_bfloat16*)(smem + BS_LO);
    #pragma unroll 1
    for (int k0 = 0; k0 < D; k0 += 16) {
        FragA ah[2], al[2];
        FragB bh[2], bl[2];
        #pragma unroll
        for (int i = 0; i < 2; ++i) {
            wmma::load_matrix_sync(ah[i], pah + (wm * 32 + 16 * i) * PA + k0, PA);
            wmma::load_matrix_sync(al[i], pal + (wm * 32 + 16 * i) * PA + k0, PA);
            wmma::load_matrix_sync(bh[i], pbh + k0 * PA + wn * 32 + 16 * i, PA);
            wmma::load_matrix_sync(bl[i], pbl + k0 * PA + wn * 32 + 16 * i, PA);
        }
        #pragma unroll
        for (int i = 0; i < 2; ++i)
            #pragma unroll
            for (int j = 0; j < 2; ++j) {
                wmma::mma_sync(acc[i][j], ah[i], bh[j], acc[i][j]);
                wmma::mma_sync(acc[i][j], al[i], bh[j], acc[i][j]);
                wmma::mma_sync(acc[i][j], ah[i], bl[j], acc[i][j]);
            }
    }
}

__device__ __forceinline__ void store_acc(char* smem, FragC acc[2][2], int wm, int wn) {
    float* scr = (float*)(smem + SCR);
    #pragma unroll
    for (int i = 0; i < 2; ++i)
        #pragma unroll
        for (int j = 0; j < 2; ++j)
            wmma::store_matrix_sync(scr + (wm * 32 + 16 * i) * 132 + wn * 32 + 16 * j,
                                    acc[i][j], 132, wmma::mem_row_major);
}

__global__ void __launch_bounds__(512, 1)
k_main(const float* __restrict__ h, const float* __restrict__ b_lin,
       float* __restrict__ out) {
    extern __shared__ char smem[];
    float* scr = (float*)(smem + SCR);
    float* sb = (float*)(smem + SB);
    int tid = threadIdx.x;
    int w = tid >> 5;
    int wm = w >> 2, wn = w & 3;
    int nb = blockIdx.x * D;
    float* out_h = out + (long long)NN * D;

    // prologue: xa and h bf16 hi/lo panels (padded rows, no swizzle)
    for (int idx = tid; idx < D * 64; idx += 512) {
        int row = idx >> 6;
        int k = (idx & 63) * 2;
        int node = nb + row;
        float a0 = 0, a1 = 0, h0 = 0, h1 = 0;
        if (node < NN) {
            float dv = g_dinv[node];
            float2 va = *(const float2*)(g_agg + node * D + k);
            a0 = dv * va.x; a1 = dv * va.y;
            float2 vh = *(const float2*)(h + node * D + k);
            h0 = vh.x; h1 = vh.y;
        }
        int boff = (row * PA + k) * 2;
        u32 hi, lo;
        split2(a0, a1, hi, lo);
        *(u32*)(smem + XA_HI + boff) = hi;
        *(u32*)(smem + XA_LO + boff) = lo;
        split2(h0, h1, hi, lo);
        *(u32*)(smem + H_HI + boff) = hi;
        *(u32*)(smem + H_LO + boff) = lo;
    }
    if (tid < 512) sb[tid] = (tid < 384) ? g_bf[tid] : b_lin[tid - 384];
    __syncthreads();

    FragC acc[2][2];

    // ================= stage Z: Zpre = xa@Wfz + h@Wlzb =================
    #pragma unroll
    for (int i = 0; i < 2; ++i)
        #pragma unroll
        for (int j = 0; j < 2; ++j) wmma::fill_fragment(acc[i][j], 0.0f);
    copyB(smem, 0, tid); __syncthreads();
    gemm_mat(smem, XA_HI, XA_LO, acc, wm, wn); __syncthreads();
    copyB(smem, 1, tid); __syncthreads();
    gemm_mat(smem, H_HI, H_LO, acc, wm, wn); __syncthreads();
    store_acc(smem, acc, wm, wn); __syncthreads();
    // epilogue: z = sigm(pre+bz) -> stage in out[z region] (rewritten at L)
    for (int e = tid; e < D * 32; e += 512) {
        int r = e >> 5, c = (e & 31) * 4;
        int node = nb + r;
        if (node < NN) {
            float4 p = *(float4*)(scr + r * 132 + c);
            float4 z = make_float4(sigm(p.x + sb[c]), sigm(p.y + sb[c + 1]),
                                   sigm(p.z + sb[c + 2]), sigm(p.w + sb[c + 3]));
            *(float4*)(out + (long long)node * D + c) = z;
        }
    }
    __syncthreads();

    // ================= stage R: Rpre = xa@Wfr + h@Wlrb =================
    #pragma unroll
    for (int i = 0; i < 2; ++i)
        #pragma unroll
        for (int j = 0; j < 2; ++j) wmma::fill_fragment(acc[i][j], 0.0f);
    copyB(smem, 2, tid); __syncthreads();
    gemm_mat(smem, XA_HI, XA_LO, acc, wm, wn); __syncthreads();
    copyB(smem, 3, tid); __syncthreads();
    gemm_mat(smem, H_HI, H_LO, acc, wm, wn); __syncthreads();
    store_acc(smem, acc, wm, wn); __syncthreads();
    // epilogue: hr = h * sigm(pre+br) -> hi/lo panels (overwrites h panels)
    for (int e = tid; e < D * 32; e += 512) {
        int r = e >> 5, c = (e & 31) * 4;
        int node = nb + r;
        float4 p = *(float4*)(scr + r * 132 + c);
        float4 hv = make_float4(0, 0, 0, 0);
        if (node < NN) hv = *(const float4*)(h + (long long)node * D + c);
        float4 hr;
        hr.x = hv.x * sigm(p.x + sb[D + c]);
        hr.y = hv.y * sigm(p.y + sb[D + c + 1]);
        hr.z = hv.z * sigm(p.z + sb[D + c + 2]);
        hr.w = hv.w * sigm(p.w + sb[D + c + 3]);
        int boff = (r * PA + c) * 2;
        u32 hi, lo;
        split2(hr.x, hr.y, hi, lo);
        *(u32*)(smem + H_HI + boff) = hi;
        *(u32*)(smem + H_LO + boff) = lo;
        split2(hr.z, hr.w, hi, lo);
        *(u32*)(smem + H_HI + boff + 4) = hi;
        *(u32*)(smem + H_LO + boff + 4) = lo;
    }
    __syncthreads();

    // ================= stage H: Hpre = xa@Wfh + hr@Wlhb =================
    #pragma unroll
    for (int i = 0; i < 2; ++i)
        #pragma unroll
        for (int j = 0; j < 2; ++j) wmma::fill_fragment(acc[i][j], 0.0f);
    copyB(smem, 4, tid); __syncthreads();
    gemm_mat(smem, XA_HI, XA_LO, acc, wm, wn); __syncthreads();
    copyB(smem, 5, tid); __syncthreads();
    gemm_mat(smem, H_HI, H_LO, acc, wm, wn); __syncthreads();
    store_acc(smem, acc, wm, wn); __syncthreads();
    // epilogue: h0 = z*h + (1-z)*tanh(pre+bh); store h0; relu(h0) -> xa panels
    for (int e = tid; e < D * 32; e += 512) {
        int r = e >> 5, c = (e & 31) * 4;
        int node = nb + r;
        float h0v[4] = {0, 0, 0, 0};
        if (node < NN) {
            float4 p = *(float4*)(scr + r * 132 + c);
            float4 hv = *(const float4*)(h + (long long)node * D + c);
            float4 zv = *(const float4*)(out + (long long)node * D + c);
            float pr[4] = {p.x, p.y, p.z, p.w};
            float hh[4] = {hv.x, hv.y, hv.z, hv.w};
            float zz[4] = {zv.x, zv.y, zv.z, zv.w};
            #pragma unroll
            for (int q = 0; q < 4; ++q) {
                float Ht = tanhf(pr[q] + sb[2 * D + c + q]);
                h0v[q] = zz[q] * hh[q] + (1.0f - zz[q]) * Ht;
            }
            *(float4*)(out_h + (long long)node * D + c) =
                make_float4(h0v[0], h0v[1], h0v[2], h0v[3]);
        }
        int boff = (r * PA + c) * 2;
        u32 hi, lo;
        split2(fmaxf(h0v[0], 0.0f), fmaxf(h0v[1], 0.0f), hi, lo);
        *(u32*)(smem + XA_HI + boff) = hi;
        *(u32*)(smem + XA_LO + boff) = lo;
        split2(fmaxf(h0v[2], 0.0f), fmaxf(h0v[3], 0.0f), hi, lo);
        *(u32*)(smem + XA_HI + boff + 4) = hi;
        *(u32*)(smem + XA_LO + boff + 4) = lo;
    }
    __syncthreads();

    // ================= stage L: z_out = relu(h0)@Wlin + b_lin ============
    #pragma unroll
    for (int i = 0; i < 2; ++i)
        #pragma unroll
        for (int j = 0; j < 2; ++j) wmma::fill_fragment(acc[i][j], 0.0f);
    copyB(smem, 6, tid); __syncthreads();
    gemm_mat(smem, XA_HI, XA_LO, acc, wm, wn); __syncthreads();
    store_acc(smem, acc, wm, wn); __syncthreads();
    for (int e = tid; e < D * 32; e += 512) {
        int r = e >> 5, c = (e & 31) * 4;
        int node = nb + r;
        if (node < NN) {
            float4 p = *(float4*)(scr + r * 132 + c);
            p.x += sb[3 * D + c];
            p.y += sb[3 * D + c + 1];
            p.z += sb[3 * D + c + 2];
            p.w += sb[3 * D + c + 3];
            *(float4*)(out + (long long)node * D + c) = p;
        }
    }
}

// ---------------- launch -----------------------------------------------------
extern "C" void kernel_launch(void* const* d_in, const int* in_sizes, int n_in,
                              void* d_out, int out_size) {
    const float* node_feat = (const float*)d_in[0];
    const int*   src       = (const int*)d_in[1];
    const int*   dst       = (const int*)d_in[2];
    const float* h         = (const float*)d_in[3];
    const float* Wc_z = (const float*)d_in[4];
    const float* bc_z = (const float*)d_in[5];
    const float* Wl_z = (const float*)d_in[6];
    const float* bl_z = (const float*)d_in[7];
    const float* Wc_r = (const float*)d_in[8];
    const float* bc_r = (const float*)d_in[9];
    const float* Wl_r = (const float*)d_in[10];
    const float* bl_r = (const float*)d_in[11];
    const float* Wc_h = (const float*)d_in[12];
    const float* bc_h = (const float*)d_in[13];
    const float* Wl_h = (const float*)d_in[14];
    const float* bl_h = (const float*)d_in[15];
    const float* W_lin = (const float*)d_in[16];
    const float* b_lin = (const float*)d_in[17];
    float* out = (float*)d_out;

    cudaFuncSetAttribute(k_main, cudaFuncAttributeMaxDynamicSharedMemorySize, SM_TOTAL);

    k_init_deg<<<(NN + 255) / 256, 256>>>();
    k_count<<<(NE + 255) / 256, 256>>>(dst);
    k_prescale<<<(NN * 32 + 255) / 256, 256>>>(node_feat);
    k_edges<<<(NE * 32) / 256, 256>>>(src, dst);
    k_fuse<<<dim3(D, 3), D>>>(Wc_z, Wl_z, bc_z, bl_z,
                              Wc_r, Wl_r, bc_r, bl_r,
                              Wc_h, Wl_h, bc_h, bl_h);
    k_prep<<<(7 * D * D + 255) / 256, 256>>>(Wl_z, Wl_r, Wl_h, W_lin);
    k_main<<<(NN + D - 1) / D, 512, SM_TOTAL>>>(h, b_lin, out);
}

// round 7
// speedup vs baseline: 4.1750x; 1.0096x over previous
#include <cuda_runtime.h>
#include <cuda_bf16.h>
#include <mma.h>
#include <math.h>

#define NN 50000
#define NE 800000
#define D 128
#define ROWS 64           // rows per CTA tile
#define PA 136            // padded panel row (bf16 elems), 272B rows
#define PAB (PA * 2)

// smem byte offsets (per-CTA total 106496)
#define XA_HI 0
#define XA_LO 17408
#define H_HI  34816
#define H_LO  52224
#define BUF0  69632       // two 17408B B quarter-buffers (ping-pong)
#define SCR   69632       // f32 scratch 64x132 (33792B) overlays buffers
#define SB    104448      // 512 f32 biases
#define SM_TOTAL (104448 + 2048)

typedef unsigned int u32;
using namespace nvcuda;
typedef wmma::fragment<wmma::matrix_a, 16, 16, 16, __nv_bfloat16, wmma::row_major> FragA;
typedef wmma::fragment<wmma::matrix_b, 16, 16, 16, __nv_bfloat16, wmma::row_major> FragB;
typedef wmma::fragment<wmma::accumulator, 16, 16, 16, float> FragC;

// ---------------- scratch (device globals; no allocation allowed) ----------
__device__ float g_deg[NN];
__device__ float g_dinv[NN];
__device__ float g_xs[NN * D];
__device__ float g_agg[NN * D];
__device__ float g_Wf[3 * D * D];
__device__ float g_bf[3 * D];
// 7 B mats (Wfz, Wlzb, Wfr, Wlrb, Wfh, Wlhb, Wlin), [k][n] bf16, hi then lo
__device__ __nv_bfloat16 g_B[7 * 32768];

__device__ __forceinline__ u32 s2u(const void* p) {
    u32 a;
    asm("{ .reg .u64 t; cvta.to.shared.u64 t, %1; cvt.u32.u64 %0, t; }"
        : "=r"(a) : "l"(p));
    return a;
}
__device__ __forceinline__ float sigm(float x) { return 1.0f / (1.0f + expf(-x)); }
__device__ __forceinline__ void split2(float x0, float x1, u32& hi, u32& lo) {
    __nv_bfloat16 h0 = __float2bfloat16(x0), h1 = __float2bfloat16(x1);
    __nv_bfloat16 l0 = __float2bfloat16(x0 - __bfloat162float(h0));
    __nv_bfloat16 l1 = __float2bfloat16(x1 - __bfloat162float(h1));
    hi = (u32)__bfloat16_as_ushort(h0) | ((u32)__bfloat16_as_ushort(h1) << 16);
    lo = (u32)__bfloat16_as_ushort(l0) | ((u32)__bfloat16_as_ushort(l1) << 16);
}

// ---------------- graph prep kernels ----------------------------------------
__global__ void k_init_deg() {
    int i = blockIdx.x * blockDim.x + threadIdx.x;
    if (i < NN) g_deg[i] = 1.0f;
}
__global__ void k_count(const int* __restrict__ dst) {
    int e = blockIdx.x * blockDim.x + threadIdx.x;
    if (e < NE) atomicAdd(&g_deg[dst[e]], 1.0f);
}
__global__ void k_prescale(const float* __restrict__ x) {
    int idx = blockIdx.x * blockDim.x + threadIdx.x;
    if (idx >= NN * 32) return;
    int i = idx >> 5, c = idx & 31;
    float dv = rsqrtf(g_deg[i]);
    float4 v = ((const float4*)x)[idx];
    v.x *= dv; v.y *= dv; v.z *= dv; v.w *= dv;
    ((float4*)g_xs)[idx] = v;
    ((float4*)g_agg)[idx] = v;
    if (c == 0) g_dinv[i] = dv;
}
__global__ void k_edges(const int* __restrict__ src, const int* __restrict__ dst) {
    int idx = blockIdx.x * blockDim.x + threadIdx.x;
    if (idx >= NE * 32) return;
    int e = idx >> 5, lane = idx & 31;
    int s = __ldg(&src[e]);
    int d2 = __ldg(&dst[e]);
    float4 v = ((const float4*)g_xs)[s * 32 + lane];
    float4* p = ((float4*)g_agg) + d2 * 32 + lane;
    asm volatile("red.global.add.v4.f32 [%0], {%1,%2,%3,%4};"
                 :: "l"(p), "f"(v.x), "f"(v.y), "f"(v.z), "f"(v.w) : "memory");
}

// ---------------- weight fusion + bf16 split ---------------------------------
__global__ void k_fuse(const float* __restrict__ Wc_z, const float* __restrict__ Wl_z,
                       const float* __restrict__ bc_z, const float* __restrict__ bl_z,
                       const float* __restrict__ Wc_r, const float* __restrict__ Wl_r,
                       const float* __restrict__ bc_r, const float* __restrict__ bl_r,
                       const float* __restrict__ Wc_h, const float* __restrict__ Wl_h,
                       const float* __restrict__ bc_h, const float* __restrict__ bl_h) {
    int g = blockIdx.y;
    const float* Wc = (g == 0) ? Wc_z : (g == 1) ? Wc_r : Wc_h;
    const float* Wl = (g == 0) ? Wl_z : (g == 1) ? Wl_r : Wl_h;
    const float* bc = (g == 0) ? bc_z : (g == 1) ? bc_r : bc_h;
    const float* bl = (g == 0) ? bl_z : (g == 1) ? bl_r : bl_h;
    int i = blockIdx.x;
    int j = threadIdx.x;
    float s = 0.0f;
    #pragma unroll 8
    for (int k = 0; k < D; ++k) s += Wc[i * D + k] * Wl[k * D + j];
    g_Wf[g * D * D + i * D + j] = s;
    if (i == 0) {
        float b = bl[j];
        #pragma unroll 8
        for (int k = 0; k < D; ++k) b += bc[k] * Wl[k * D + j];
        g_bf[g * D + j] = b;
    }
}

__global__ void k_prep(const float* __restrict__ Wl_z, const float* __restrict__ Wl_r,
                       const float* __restrict__ Wl_h, const float* __restrict__ W_lin) {
    int idx = blockIdx.x * blockDim.x + threadIdx.x;
    if (idx >= 7 * D * D) return;
    int m = idx / (D * D);
    int r = idx % (D * D);
    int k = r / D, n = r % D;
    float w;
    switch (m) {
        case 0: w = g_Wf[k * D + n]; break;
        case 1: w = Wl_z[(D + k) * D + n]; break;
        case 2: w = g_Wf[D * D + k * D + n]; break;
        case 3: w = Wl_r[(D + k) * D + n]; break;
        case 4: w = g_Wf[2 * D * D + k * D + n]; break;
        case 5: w = Wl_h[(D + k) * D + n]; break;
        default: w = W_lin[k * D + n]; break;
    }
    __nv_bfloat16 hi = __float2bfloat16(w);
    __nv_bfloat16 lo = __float2bfloat16(w - __bfloat162float(hi));
    g_B[m * 32768 + k * D + n] = hi;
    g_B[m * 32768 + 16384 + k * D + n] = lo;
}

// ---------------- main fused GRU kernel --------------------------------------
// prefetch one k-quarter (32 k-rows, hi+lo) of matrix `mat` into buffer `buf`
__device__ __forceinline__ void pfq(u32 smb, int buf, int mat, int q, int tid) {
    const char* src = (const char*)g_B + mat * 65536;
    u32 dst = smb + BUF0 + buf * 17408;
    #pragma unroll
    for (int e = tid; e < 1024; e += 256) {
        int half = e >> 9;          // 0 = hi, 1 = lo
        int r = (e >> 4) & 31;
        int c = e & 15;
        const char* s = src + half * 32768 + (q * 32 + r) * 256 + c * 16;
        u32 d = dst + half * 8704 + r * PAB + c * 16;
        asm volatile("cp.async.cg.shared.global [%0], [%1], 16;" :: "r"(d), "l"(s));
    }
    asm volatile("cp.async.commit_group;");
}

// MMA over one k-quarter: A panel cols [32q,32q+32), B quarter buffer
__device__ __forceinline__ void gemm_q(const char* smem, int aoff, int boff,
                                       FragC acc[2][2], int wm, int wn, int q) {
    const __nv_bfloat16* pah = (const __nv_bfloat16*)(smem + aoff);
    const __nv_bfloat16* pal = (const __nv_bfloat16*)(smem + aoff + 17408);
    const __nv_bfloat16* pbh = (const __nv_bfloat16*)(smem + boff);
    const __nv_bfloat16* pbl = (const __nv_bfloat16*)(smem + boff + 8704);
    #pragma unroll
    for (int k0 = 0; k0 < 32; k0 += 16) {
        FragA ah[2], al[2];
        FragB bh[2], bl[2];
        #pragma unroll
        for (int i = 0; i < 2; ++i) {
            wmma::load_matrix_sync(ah[i], pah + (wm * 32 + 16 * i) * PA + q * 32 + k0, PA);
            wmma::load_matrix_sync(al[i], pal + (wm * 32 + 16 * i) * PA + q * 32 + k0, PA);
            wmma::load_matrix_sync(bh[i], pbh + k0 * PA + wn * 32 + 16 * i, PA);
            wmma::load_matrix_sync(bl[i], pbl + k0 * PA + wn * 32 + 16 * i, PA);
        }
        #pragma unroll
        for (int i = 0; i < 2; ++i)
            #pragma unroll
            for (int j = 0; j < 2; ++j) {
                wmma::mma_sync(acc[i][j], ah[i], bh[j], acc[i][j]);
                wmma::mma_sync(acc[i][j], al[i], bh[j], acc[i][j]);
                wmma::mma_sync(acc[i][j], ah[i], bl[j], acc[i][j]);
            }
    }
}

// run one stage: NMAT matrix contributions, pipelined quarter prefetch,
// result left in SCR (f32, stride 132).
template <int NMAT>
__device__ __forceinline__ void run_stage(char* smem, u32 smb,
                                          int m0, int m1, int a0, int a1,
                                          FragC acc[2][2], int tid, int wm, int wn,
                                          bool pre_issued) {
    #pragma unroll
    for (int i = 0; i < 2; ++i)
        #pragma unroll
        for (int j = 0; j < 2; ++j) wmma::fill_fragment(acc[i][j], 0.0f);
    if (!pre_issued) pfq(smb, 0, m0, 0, tid);
    const int TQ = NMAT * 4;
    #pragma unroll 1
    for (int t = 0; t < TQ; ++t) {
        int buf = t & 1;
        if (t + 1 < TQ) {
            pfq(smb, buf ^ 1, ((t + 1) >> 2) ? m1 : m0, (t + 1) & 3, tid);
            asm volatile("cp.async.wait_group 1;");
        } else {
            asm volatile("cp.async.wait_group 0;");
        }
        __syncthreads();
        gemm_q(smem, (t >> 2) ? a1 : a0, BUF0 + buf * 17408, acc, wm, wn, t & 3);
        __syncthreads();
    }
    float* scr = (float*)(smem + SCR);
    #pragma unroll
    for (int i = 0; i < 2; ++i)
        #pragma unroll
        for (int j = 0; j < 2; ++j)
            wmma::store_matrix_sync(scr + (wm * 32 + 16 * i) * 132 + wn * 32 + 16 * j,
                                    acc[i][j], 132, wmma::mem_row_major);
    __syncthreads();
}

__global__ void __launch_bounds__(256, 2)
k_main(const float* __restrict__ h, const float* __restrict__ b_lin,
       float* __restrict__ out) {
    extern __shared__ char smem[];
    u32 smb = s2u(smem);
    float* scr = (float*)(smem + SCR);
    float* sb = (float*)(smem + SB);
    int tid = threadIdx.x;
    int w = tid >> 5;
    int wm = w >> 2, wn = w & 3;     // 2 x 4 warp grid, 32x32 warp tiles
    int nb = blockIdx.x * ROWS;
    float* out_h = out + (long long)NN * D;

    // overlap first B prefetch with the prologue
    pfq(smb, 0, 0, 0, tid);

    // prologue: xa and h bf16 hi/lo panels
    for (int idx = tid; idx < ROWS * 64; idx += 256) {
        int row = idx >> 6;
        int k = (idx & 63) * 2;
        int node = nb + row;
        float a0 = 0, a1 = 0, h0 = 0, h1 = 0;
        if (node < NN) {
            float dv = g_dinv[node];
            float2 va = *(const float2*)(g_agg + node * D + k);
            a0 = dv * va.x; a1 = dv * va.y;
            float2 vh = *(const float2*)(h + node * D + k);
            h0 = vh.x; h1 = vh.y;
        }
        int boff = (row * PA + k) * 2;
        u32 hi, lo;
        split2(a0, a1, hi, lo);
        *(u32*)(smem + XA_HI + boff) = hi;
        *(u32*)(smem + XA_LO + boff) = lo;
        split2(h0, h1, hi, lo);
        *(u32*)(smem + H_HI + boff) = hi;
        *(u32*)(smem + H_LO + boff) = lo;
    }
    for (int q = tid; q < 512; q += 256)
        sb[q] = (q < 384) ? g_bf[q] : b_lin[q - 384];
    __syncthreads();

    FragC acc[2][2];

    // ===== stage Z =====
    run_stage<2>(smem, smb, 0, 1, XA_HI, H_HI, acc, tid, wm, wn, true);
    for (int e = tid; e < ROWS * 32; e += 256) {
        int r = e >> 5, c = (e & 31) * 4;
        int node = nb + r;
        if (node < NN) {
            float4 p = *(float4*)(scr + r * 132 + c);
            float4 z = make_float4(sigm(p.x + sb[c]), sigm(p.y + sb[c + 1]),
                                   sigm(p.z + sb[c + 2]), sigm(p.w + sb[c + 3]));
            *(float4*)(out + (long long)node * D + c) = z;  // stage z (rewritten at L)
        }
    }
    __syncthreads();

    // ===== stage R =====
    run_stage<2>(smem, smb, 2, 3, XA_HI, H_HI, acc, tid, wm, wn, false);
    for (int e = tid; e < ROWS * 32; e += 256) {
        int r = e >> 5, c = (e & 31) * 4;
        int node = nb + r;
        float4 p = *(float4*)(scr + r * 132 + c);
        float4 hv = make_float4(0, 0, 0, 0);
        if (node < NN) hv = *(const float4*)(h + (long long)node * D + c);
        float4 hr;
        hr.x = hv.x * sigm(p.x + sb[D + c]);
        hr.y = hv.y * sigm(p.y + sb[D + c + 1]);
        hr.z = hv.z * sigm(p.z + sb[D + c + 2]);
        hr.w = hv.w * sigm(p.w + sb[D + c + 3]);
        int boff = (r * PA + c) * 2;
        u32 hi, lo;
        split2(hr.x, hr.y, hi, lo);
        *(u32*)(smem + H_HI + boff) = hi;
        *(u32*)(smem + H_LO + boff) = lo;
        split2(hr.z, hr.w, hi, lo);
        *(u32*)(smem + H_HI + boff + 4) = hi;
        *(u32*)(smem + H_LO + boff + 4) = lo;
    }
    __syncthreads();

    // ===== stage H =====
    run_stage<2>(smem, smb, 4, 5, XA_HI, H_HI, acc, tid, wm, wn, false);
    for (int e = tid; e < ROWS * 32; e += 256) {
        int r = e >> 5, c = (e & 31) * 4;
        int node = nb + r;
        float h0v[4] = {0, 0, 0, 0};
        if (node < NN) {
            float4 p = *(float4*)(scr + r * 132 + c);
            float4 hv = *(const float4*)(h + (long long)node * D + c);
            float4 zv = *(const float4*)(out + (long long)node * D + c);
            float pr[4] = {p.x, p.y, p.z, p.w};
            float hh[4] = {hv.x, hv.y, hv.z, hv.w};
            float zz[4] = {zv.x, zv.y, zv.z, zv.w};
            #pragma unroll
            for (int q = 0; q < 4; ++q) {
                float Ht = tanhf(pr[q] + sb[2 * D + c + q]);
                h0v[q] = zz[q] * hh[q] + (1.0f - zz[q]) * Ht;
            }
            *(float4*)(out_h + (long long)node * D + c) =
                make_float4(h0v[0], h0v[1], h0v[2], h0v[3]);
        }
        int boff = (r * PA + c) * 2;
        u32 hi, lo;
        split2(fmaxf(h0v[0], 0.0f), fmaxf(h0v[1], 0.0f), hi, lo);
        *(u32*)(smem + XA_HI + boff) = hi;
        *(u32*)(smem + XA_LO + boff) = lo;
        split2(fmaxf(h0v[2], 0.0f), fmaxf(h0v[3], 0.0f), hi, lo);
        *(u32*)(smem + XA_HI + boff + 4) = hi;
        *(u32*)(smem + XA_LO + boff + 4) = lo;
    }
    __syncthreads();

    // ===== stage L =====
    run_stage<1>(smem, smb, 6, 6, XA_HI, XA_HI, acc, tid, wm, wn, false);
    for (int e = tid; e < ROWS * 32; e += 256) {
        int r = e >> 5, c = (e & 31) * 4;
        int node = nb + r;
        if (node < NN) {
            float4 p = *(float4*)(scr + r * 132 + c);
            p.x += sb[3 * D + c];
            p.y += sb[3 * D + c + 1];
            p.z += sb[3 * D + c + 2];
            p.w += sb[3 * D + c + 3];
            *(float4*)(out + (long long)node * D + c) = p;
        }
    }
}

// ---------------- launch -----------------------------------------------------
extern "C" void kernel_launch(void* const* d_in, const int* in_sizes, int n_in,
                              void* d_out, int out_size) {
    const float* node_feat = (const float*)d_in[0];
    const int*   src       = (const int*)d_in[1];
    const int*   dst       = (const int*)d_in[2];
    const float* h         = (const float*)d_in[3];
    const float* Wc_z = (const float*)d_in[4];
    const float* bc_z = (const float*)d_in[5];
    const float* Wl_z = (const float*)d_in[6];
    const float* bl_z = (const float*)d_in[7];
    const float* Wc_r = (const float*)d_in[8];
    const float* bc_r = (const float*)d_in[9];
    const float* Wl_r = (const float*)d_in[10];
    const float* bl_r = (const float*)d_in[11];
    const float* Wc_h = (const float*)d_in[12];
    const float* bc_h = (const float*)d_in[13];
    const float* Wl_h = (const float*)d_in[14];
    const float* bl_h = (const float*)d_in[15];
    const float* W_lin = (const float*)d_in[16];
    const float* b_lin = (const float*)d_in[17];
    float* out = (float*)d_out;

    cudaFuncSetAttribute(k_main, cudaFuncAttributeMaxDynamicSharedMemorySize, SM_TOTAL);

    k_init_deg<<<(NN + 255) / 256, 256>>>();
    k_count<<<(NE + 255) / 256, 256>>>(dst);
    k_prescale<<<(NN * 32 + 255) / 256, 256>>>(node_feat);
    k_edges<<<(NE * 32) / 256, 256>>>(src, dst);
    k_fuse<<<dim3(D, 3), D>>>(Wc_z, Wl_z, bc_z, bl_z,
                              Wc_r, Wl_r, bc_r, bl_r,
                              Wc_h, Wl_h, bc_h, bl_h);
    k_prep<<<(7 * D * D + 255) / 256, 256>>>(Wl_z, Wl_r, Wl_h, W_lin);
    k_main<<<(NN + ROWS - 1) / ROWS, 256, SM_TOTAL>>>(h, b_lin, out);
}